// round 13
// baseline (speedup 1.0000x reference)
#include <cuda_runtime.h>
#include <cstdint>

#define UNITS 65
#define G4    260          // 4*UNITS
#define BATCH 50
#define SEQ   8192
#define NROWS (BATCH * SEQ)   // 409600

// ---------------- scratch (device globals; no runtime allocation) ----------------
__device__ float g_zpre[(size_t)NROWS * G4];     // x@W + b, precomputed per (b,t)
__device__ float g_h2s[(size_t)NROWS * UNITS];   // layer-2 hidden stream (A -> B)
__device__ float g_h3[(size_t)NROWS * UNITS];    // layer-3 hidden states (ys)
__device__ unsigned int g_flag[BATCH];           // per-row completed-step counter

// ---------------- f32x2 helpers (Blackwell packed fp32 FMA) ----------------
__device__ __forceinline__ unsigned long long pack2(float lo, float hi) {
    unsigned long long v;
    asm("mov.b64 %0, {%1, %2};" : "=l"(v) : "f"(lo), "f"(hi));
    return v;
}
__device__ __forceinline__ unsigned long long ffma2(unsigned long long a,
                                                    unsigned long long b,
                                                    unsigned long long c) {
    unsigned long long d;
    asm("fma.rn.f32x2 %0, %1, %2, %3;" : "=l"(d) : "l"(a), "l"(b), "l"(c));
    return d;
}
__device__ __forceinline__ unsigned long long fadd2(unsigned long long a,
                                                    unsigned long long b) {
    unsigned long long d;
    asm("add.rn.f32x2 %0, %1, %2;" : "=l"(d) : "l"(a), "l"(b));
    return d;
}
__device__ __forceinline__ float hsum4(unsigned long long a0, unsigned long long a1) {
    unsigned long long s = fadd2(a0, a1);
    float x0, x1;
    asm("mov.b64 {%0, %1}, %2;" : "=f"(x0), "=f"(x1) : "l"(s));
    return x0 + x1;
}

// dot over K=65 (padded to 66 with zero): sh must be 16B-aligned float[68] with
// sh[65] == 0; col[33] holds weight pairs (col[32].hi == 0).
__device__ __forceinline__ void dot33(const float* __restrict__ sh,
                                      const unsigned long long* col,
                                      unsigned long long& a0,
                                      unsigned long long& a1) {
    const ulonglong2* hp = reinterpret_cast<const ulonglong2*>(sh);
#pragma unroll
    for (int m = 0; m < 16; m++) {
        ulonglong2 p = hp[m];
        a0 = ffma2(p.x, col[2 * m + 0], a0);
        a1 = ffma2(p.y, col[2 * m + 1], a1);
    }
    unsigned long long last = *reinterpret_cast<const unsigned long long*>(sh + 64);
    a0 = ffma2(last, col[32], a0);
}

// ---------------- acquire/release flag helpers ----------------
__device__ __forceinline__ unsigned int ld_acq(const unsigned int* p) {
    unsigned int v;
    asm volatile("ld.acquire.gpu.u32 %0, [%1];" : "=r"(v) : "l"(p) : "memory");
    return v;
}
__device__ __forceinline__ void st_rel(unsigned int* p, unsigned int v) {
    asm volatile("st.release.gpu.u32 [%0], %1;" :: "l"(p), "r"(v) : "memory");
}

// ---------------- fast activations (ex2/rcp approx: ~1e-6 rel err) ----------------
__device__ __forceinline__ float fast_ex2(float x) {
    float y; asm("ex2.approx.f32 %0, %1;" : "=f"(y) : "f"(x)); return y;
}
__device__ __forceinline__ float fast_rcp(float x) {
    float y; asm("rcp.approx.f32 %0, %1;" : "=f"(y) : "f"(x)); return y;
}
#define LOG2E 1.4426950408889634f
__device__ __forceinline__ float sigm_f(float x) {
    return fast_rcp(1.0f + fast_ex2(-x * LOG2E));
}
__device__ __forceinline__ float tanh_f(float x) {
    return fmaf(-2.0f, fast_rcp(1.0f + fast_ex2(2.0f * LOG2E * x)), 1.0f);
}
__device__ __forceinline__ float act_lstm(const float* __restrict__ z, int ak,
                                          float& c) {
    float zi = z[ak], zf = z[ak + UNITS];
    float zg = z[ak + 2 * UNITS], zo = z[ak + 3 * UNITS];
    c = sigm_f(zf) * c + sigm_f(zi) * tanh_f(zg);
    return sigm_f(zo) * tanh_f(c);
}

// ---------------- kernel 0: reset flags (every launch / graph replay) ------------
__global__ void init_kernel() {
    if (threadIdx.x < BATCH) g_flag[threadIdx.x] = 0;
}

// ---------------- kernel 1: zpre = x @ W + b  (all rows, parallel) ----------------
__global__ void __launch_bounds__(G4) pre_kernel(const float* __restrict__ x,
                                                 const float* __restrict__ W,
                                                 const float* __restrict__ b) {
    const int tid = threadIdx.x;           // 0..259  -> gate column
    const int rsub = tid / UNITS;          // 0..3    (x-row loader role)
    const int jl = tid - rsub * UNITS;     // 0..64

    unsigned long long wcol[33];
#pragma unroll
    for (int m = 0; m < 32; m++)
        wcol[m] = pack2(W[(2 * m) * G4 + tid], W[(2 * m + 1) * G4 + tid]);
    wcol[32] = pack2(W[64 * G4 + tid], 0.0f);
    const float bj = b[tid];

    __shared__ __align__(16) float sh_x[4][68];
    if (tid < 12) sh_x[tid / 3][65 + tid % 3] = 0.0f;   // zero pads once
    __syncthreads();

    for (size_t row0 = (size_t)blockIdx.x * 4; row0 < NROWS;
         row0 += (size_t)gridDim.x * 4) {
        __syncthreads();   // previous iteration's reads complete
        sh_x[rsub][jl] = x[(row0 + rsub) * UNITS + jl];
        __syncthreads();
#pragma unroll
        for (int r = 0; r < 4; r++) {
            unsigned long long a0 = 0ull, a1 = 0ull;
            dot33(sh_x[r], wcol, a0, a1);
            g_zpre[(row0 + r) * G4 + tid] = bj + hsum4(a0, a1);
        }
    }
}

// ---------------- kernel 2: layer-wavefront recurrence, 2 SMs per batch row ------
// Grid = 100 blocks (single wave on 148 SMs), 352 threads = 11 warps.
// Warp roles (both A and B blocks), chosen for exact SMSP balance (wid%4):
//   w0-w7 (j<256)        : dot threads, output o=j. 2 dot warps per SMSP.
//   w8    (j 256..287)   : act units 0..31                       (SMSP0)
//   w9    (j 288..319)   : A: act units 32..63 / B: P1 fetch warp, P2 act 32..63
//   w10   (j 320..351)   : lane0: act unit 64; lane2: flag pub (A only);
//                          lanes4-7: dot outputs 256..259        (SMSP2)
// No warp mixes a full dot33 with the MUFU act chain in the same phase.
//   bid <  50 : "A" block -> layers 1+2, 3 phases/step (X,Y,Z)
//   bid >= 50 : "B" block -> layer 3, 2 phases/step
// Deadlock-freedom: single wave (100 < 148 SMs); A never waits on B; A always
// publishes flag=SEQ after its loop, so every B spin terminates; flags are
// reset by init_kernel before rec2 in the same stream on every graph replay.
__global__ void __launch_bounds__(352, 1) rec2_kernel(const float* __restrict__ W,
                                                      const float* __restrict__ U,
                                                      const float* __restrict__ b) {
    const int j = threadIdx.x;
    const bool isA = (blockIdx.x < BATCH);
    const int row = isA ? blockIdx.x : (blockIdx.x - BATCH);

    __shared__ __align__(16) float sh_ha[68], sh_hb[68];   // A: h1,h2 / B: h3,(unused)
    __shared__ __align__(16) float sh_buf[2][68];          // B: h2 double buffer
    __shared__ float sh_za[G4], sh_zb[G4];                 // A: z1,z2 / B: z3,(unused)

    // ---- role decode ----
    const bool dotA = (j < 256);
    const bool dotX = (j >= 324 && j < 328);            // outputs 256..259 on w10
    const bool is_dot = dotA || dotX;
    const int  o = dotA ? j : (dotX ? (j - 68) : 0);    // dot output index
    const bool is_act = (j >= 256 && j < 320) || (j == 320);
    const int  au = (j == 320) ? 64 : (j - 256);        // act unit (valid if is_act)
    const bool is_pub = (j == 322);

    // ---- weights in registers on dot threads ----
    unsigned long long wcol[33], ucol[33];
    float bj = 0.0f;
    if (is_dot) {
#pragma unroll
        for (int m = 0; m < 32; m++) {
            wcol[m] = pack2(W[(2 * m) * G4 + o], W[(2 * m + 1) * G4 + o]);
            ucol[m] = pack2(U[(2 * m) * G4 + o], U[(2 * m + 1) * G4 + o]);
        }
        wcol[32] = pack2(W[64 * G4 + o], 0.0f);
        ucol[32] = pack2(U[64 * G4 + o], 0.0f);
        bj = b[o];
    }
    if (j < 68) {
        sh_ha[j] = 0.0f; sh_hb[j] = 0.0f;
        sh_buf[0][j] = 0.0f; sh_buf[1][j] = 0.0f;
    }

    if (isA) {
        // ================= A: layers 1 + 2 (3 phases/step) =================
        const float* __restrict__ zpre = g_zpre + (size_t)row * SEQ * G4;
        float* __restrict__ h2out = g_h2s + (size_t)row * SEQ * UNITS;
        unsigned int* flag = &g_flag[row];

        float c1 = 0.f, c2 = 0.f;
        float u2v = 0.f;
        float zp = 0.f, zp_next = 0.f;       // 2-step rolling zpre prefetch

        if (is_dot) {
            sh_za[o] = zpre[o];              // z1(0) = zpre(0)  (h1(-1)=0)
            zp = zpre[(size_t)1 * G4 + o];   // zpre(1)  (SEQ >= 3)
            zp_next = zpre[(size_t)2 * G4 + o];
        }
        __syncthreads();

        for (int t = 0; t < SEQ; t++) {
            // ---- X: u2 = h2(t-1)@U  ||  act1(z1(t))->h1  ||  flag pub ----
            if (is_dot) {
                unsigned long long a0 = 0ull, a1 = 0ull;
                dot33(sh_hb, ucol, a0, a1);
                u2v = hsum4(a0, a1);
            } else if (is_act) {
                sh_ha[au] = act_lstm(sh_za, au, c1);
            } else if (is_pub && t > 0 && (t & 3) == 0) {
                __threadfence();             // h2 STGs of steps < t are pre-barrier
                st_rel(flag, (unsigned)t);   // t steps fully completed
            }
            __syncthreads();

            // ---- Y: z2 = h1@W + u2 + b ----
            if (is_dot) {
                unsigned long long a0 = 0ull, a1 = 0ull;
                dot33(sh_ha, wcol, a0, a1);
                sh_zb[o] = bj + u2v + hsum4(a0, a1);
            }
            __syncthreads();

            // ---- Z: u1 = h1@U, z1(t+1) = zp + u1, roll prefetch ----
            //      || act2(z2)->h2 + STG h2
            if (is_dot) {
                unsigned long long a0 = 0ull, a1 = 0ull;
                dot33(sh_ha, ucol, a0, a1);
                sh_za[o] = zp + hsum4(a0, a1);
                zp = zp_next;
                int ti = (t + 3 < SEQ) ? (t + 3) : (SEQ - 1);
                zp_next = zpre[(size_t)ti * G4 + o];
            } else if (is_act) {
                float hn = act_lstm(sh_zb, au, c2);
                sh_hb[au] = hn;
                h2out[(size_t)t * UNITS + au] = hn;
            }
            __syncthreads();
        }
        if (is_pub) {                        // final publication (B depends on it)
            __threadfence();
            st_rel(flag, (unsigned)SEQ);
        }
    } else {
        // ================= B: layer 3 (2 phases/step) =================
        const float* __restrict__ h2in = g_h2s + (size_t)row * SEQ * UNITS;
        float* __restrict__ h3out = g_h3 + (size_t)row * SEQ * UNITS;
        const unsigned int* flag = &g_flag[row];
        const int lane = (j >= 288 && j < 320) ? (j - 288) : -1;  // w9 fetch warp
        float c3 = 0.f;

        // initial fetch: h2(0) -> buf[0]
        if (lane >= 0) {
            while (ld_acq(flag) < 1u) __nanosleep(64);
            for (int u = lane; u < UNITS; u += 32)
                sh_buf[0][u] = h2in[u];
        }
        __syncthreads();

        for (int t = 0; t < SEQ; t++) {
            // P1: z3 = h2(t)@W + h3(t-1)@U + b  ||  w9: fetch h2(t+1)
            if (is_dot) {
                unsigned long long a0 = 0ull, a1 = 0ull;
                dot33(sh_buf[t & 1], wcol, a0, a1);
                dot33(sh_ha, ucol, a0, a1);            // sh_ha = h3
                sh_za[o] = bj + hsum4(a0, a1);
            } else if (lane >= 0) {
                int tsrc = (t + 1 < SEQ) ? (t + 1) : (SEQ - 1);
                while (ld_acq(flag) < (unsigned)(tsrc + 1)) __nanosleep(64);
                for (int u = lane; u < UNITS; u += 32)
                    sh_buf[(t + 1) & 1][u] = h2in[(size_t)tsrc * UNITS + u];
            }
            __syncthreads();

            // P2: act3(z3) -> h3, emit  (act units 0..31 w8, 32..63 w9, 64 w10l0)
            if (is_act) {
                float hn = act_lstm(sh_za, au, c3);
                sh_ha[au] = hn;
                h3out[(size_t)t * UNITS + au] = hn;
            }
            __syncthreads();
        }
    }
}

// ---------------- kernel 3: out = ys @ Wd + bd  (parallel) ----------------
__global__ void __launch_bounds__(G4) dense_kernel(const float* __restrict__ Wd,
                                                   const float* __restrict__ bd,
                                                   float* __restrict__ out) {
    const int tid = threadIdx.x;           // 0..259
    const int rsub = tid / UNITS;          // 0..3
    const int jl = tid - rsub * UNITS;     // 0..64 -> output column

    unsigned long long wdcol[33];
#pragma unroll
    for (int m = 0; m < 32; m++)
        wdcol[m] = pack2(Wd[(2 * m) * UNITS + jl], Wd[(2 * m + 1) * UNITS + jl]);
    wdcol[32] = pack2(Wd[64 * UNITS + jl], 0.0f);
    const float bj = bd[jl];

    __shared__ __align__(16) float sh_y[4][68];
    if (tid < 12) sh_y[tid / 3][65 + tid % 3] = 0.0f;
    __syncthreads();

    for (size_t row0 = (size_t)blockIdx.x * 4; row0 < NROWS;
         row0 += (size_t)gridDim.x * 4) {
        __syncthreads();
        sh_y[rsub][jl] = g_h3[(row0 + rsub) * UNITS + jl];
        __syncthreads();
        unsigned long long a0 = 0ull, a1 = 0ull;
        dot33(sh_y[rsub], wdcol, a0, a1);
        out[(row0 + rsub) * UNITS + jl] = bj + hsum4(a0, a1);
    }
}

// ---------------- launch ----------------
extern "C" void kernel_launch(void* const* d_in, const int* in_sizes, int n_in,
                              void* d_out, int out_size) {
    const float* x  = (const float*)d_in[0];
    const float* W  = (const float*)d_in[1];
    const float* U  = (const float*)d_in[2];
    const float* b  = (const float*)d_in[3];
    const float* Wd = (const float*)d_in[4];
    const float* bd = (const float*)d_in[5];
    float* out = (float*)d_out;

    init_kernel<<<1, 64>>>();
    pre_kernel<<<1184, G4>>>(x, W, b);
    rec2_kernel<<<2 * BATCH, 352>>>(W, U, b);
    dense_kernel<<<1184, G4>>>(Wd, bd, out);
}

// round 15
// speedup vs baseline: 1.3362x; 1.3362x over previous
#include <cuda_runtime.h>
#include <cstdint>

#define UNITS 65
#define G4    260          // 4*UNITS
#define BATCH 50
#define SEQ   8192
#define NROWS (BATCH * SEQ)   // 409600

// ---------------- scratch (device globals; no runtime allocation) ----------------
__device__ float g_zpre[(size_t)NROWS * G4];     // x@W + b, precomputed per (b,t)
__device__ float g_h2s[(size_t)NROWS * UNITS];   // layer-2 hidden stream (A -> B)
__device__ float g_h3[(size_t)NROWS * UNITS];    // layer-3 hidden states (ys)
__device__ unsigned int g_flag[BATCH];           // per-row h2-entries-available count

// ---------------- f32x2 helpers (Blackwell packed fp32 FMA) ----------------
__device__ __forceinline__ unsigned long long pack2(float lo, float hi) {
    unsigned long long v;
    asm("mov.b64 %0, {%1, %2};" : "=l"(v) : "f"(lo), "f"(hi));
    return v;
}
__device__ __forceinline__ unsigned long long ffma2(unsigned long long a,
                                                    unsigned long long b,
                                                    unsigned long long c) {
    unsigned long long d;
    asm("fma.rn.f32x2 %0, %1, %2, %3;" : "=l"(d) : "l"(a), "l"(b), "l"(c));
    return d;
}
__device__ __forceinline__ unsigned long long fadd2(unsigned long long a,
                                                    unsigned long long b) {
    unsigned long long d;
    asm("add.rn.f32x2 %0, %1, %2;" : "=l"(d) : "l"(a), "l"(b));
    return d;
}
__device__ __forceinline__ float hsum4(unsigned long long a0, unsigned long long a1) {
    unsigned long long s = fadd2(a0, a1);
    float x0, x1;
    asm("mov.b64 {%0, %1}, %2;" : "=f"(x0), "=f"(x1) : "l"(s));
    return x0 + x1;
}

// dot over K=65 (padded to 66 with zero): sh must be 16B-aligned float[68] with
// sh[65] == 0; col[33] holds weight pairs (col[32].hi == 0).
__device__ __forceinline__ void dot33(const float* __restrict__ sh,
                                      const unsigned long long* col,
                                      unsigned long long& a0,
                                      unsigned long long& a1) {
    const ulonglong2* hp = reinterpret_cast<const ulonglong2*>(sh);
#pragma unroll
    for (int m = 0; m < 16; m++) {
        ulonglong2 p = hp[m];
        a0 = ffma2(p.x, col[2 * m + 0], a0);
        a1 = ffma2(p.y, col[2 * m + 1], a1);
    }
    unsigned long long last = *reinterpret_cast<const unsigned long long*>(sh + 64);
    a0 = ffma2(last, col[32], a0);
}

// ---------------- acquire/release flag helpers ----------------
__device__ __forceinline__ unsigned int ld_acq(const unsigned int* p) {
    unsigned int v;
    asm volatile("ld.acquire.gpu.u32 %0, [%1];" : "=r"(v) : "l"(p) : "memory");
    return v;
}
__device__ __forceinline__ void st_rel(unsigned int* p, unsigned int v) {
    asm volatile("st.release.gpu.u32 [%0], %1;" :: "l"(p), "r"(v) : "memory");
}

// ---------------- fast activations (ex2/rcp approx: ~1e-6 rel err) ----------------
__device__ __forceinline__ float fast_ex2(float x) {
    float y; asm("ex2.approx.f32 %0, %1;" : "=f"(y) : "f"(x)); return y;
}
__device__ __forceinline__ float fast_rcp(float x) {
    float y; asm("rcp.approx.f32 %0, %1;" : "=f"(y) : "f"(x)); return y;
}
#define LOG2E 1.4426950408889634f
__device__ __forceinline__ float sigm_f(float x) {
    return fast_rcp(1.0f + fast_ex2(-x * LOG2E));
}
__device__ __forceinline__ float tanh_f(float x) {
    return fmaf(-2.0f, fast_rcp(1.0f + fast_ex2(2.0f * LOG2E * x)), 1.0f);
}
__device__ __forceinline__ float act_lstm(const float* __restrict__ z, int ak,
                                          float& c) {
    float zi = z[ak], zf = z[ak + UNITS];
    float zg = z[ak + 2 * UNITS], zo = z[ak + 3 * UNITS];
    c = sigm_f(zf) * c + sigm_f(zi) * tanh_f(zg);
    return sigm_f(zo) * tanh_f(c);
}

// ---------------- kernel 0: reset flags (every launch / graph replay) ------------
__global__ void init_kernel() {
    if (threadIdx.x < BATCH) g_flag[threadIdx.x] = 0;
}

// ---------------- kernel 1: zpre = x @ W + b  (all rows, parallel) ----------------
__global__ void __launch_bounds__(G4) pre_kernel(const float* __restrict__ x,
                                                 const float* __restrict__ W,
                                                 const float* __restrict__ b) {
    const int tid = threadIdx.x;           // 0..259  -> gate column
    const int rsub = tid / UNITS;          // 0..3    (x-row loader role)
    const int jl = tid - rsub * UNITS;     // 0..64

    unsigned long long wcol[33];
#pragma unroll
    for (int m = 0; m < 32; m++)
        wcol[m] = pack2(W[(2 * m) * G4 + tid], W[(2 * m + 1) * G4 + tid]);
    wcol[32] = pack2(W[64 * G4 + tid], 0.0f);
    const float bj = b[tid];

    __shared__ __align__(16) float sh_x[4][68];
    if (tid < 12) sh_x[tid / 3][65 + tid % 3] = 0.0f;   // zero pads once
    __syncthreads();

    for (size_t row0 = (size_t)blockIdx.x * 4; row0 < NROWS;
         row0 += (size_t)gridDim.x * 4) {
        __syncthreads();   // previous iteration's reads complete
        sh_x[rsub][jl] = x[(row0 + rsub) * UNITS + jl];
        __syncthreads();
#pragma unroll
        for (int r = 0; r < 4; r++) {
            unsigned long long a0 = 0ull, a1 = 0ull;
            dot33(sh_x[r], wcol, a0, a1);
            g_zpre[(row0 + r) * G4 + tid] = bj + hsum4(a0, a1);
        }
    }
}

// ---------------- kernel 2: layer-wavefront recurrence, 2 SMs per batch row ------
// Grid = 100 blocks (single wave on 148 SMs), 320 threads = 10 warps.
//   bid <  50 : "A" block -> layers 1+2, **2 phases/step** (software-pipelined:
//               the layer-2 activation of step t runs in P1 of step t+1):
//     P1: acts ONLY.  j<65: h1(t)=act(z1(t)); 65<=j<130: h2(t-1)=act(z2(t-1))+STG.
//         Same code path (only the z-pointer differs) -> no intra-warp serialization.
//     P2: dots ONLY (j<260): z2(t) = h1(t)@W + h2(t-1)@U + b  (fused 66-FFMA2 acc)
//         and z1(t+1) = zp + h1(t)@U, with 2-deep rolling zpre prefetch.
//         Pub thread j=319 (w9, idle in A): every 4 steps fence + st.release of
//         flag=t (h2[0..t-1] were stored in P1(t), pre-barrier => cumulative).
//     Epilogue: act h2(SEQ-1), STG, barrier, fence, flag=SEQ.
//   bid >= 50 : "B" block -> layer 3, 2 phases/step (unchanged from the proven
//     R11 version): P1 dot66 + w9 prefetch of h2(t+1); P2 act+emit on j<65.
// Deadlock-freedom: single wave; A never waits on B; final flag=SEQ always
// published; flags reset by init_kernel before rec2 on every graph replay.
__global__ void __launch_bounds__(320, 1) rec2_kernel(const float* __restrict__ W,
                                                      const float* __restrict__ U,
                                                      const float* __restrict__ b) {
    const int j = threadIdx.x;
    const bool isA = (blockIdx.x < BATCH);
    const int row = isA ? blockIdx.x : (blockIdx.x - BATCH);

    __shared__ __align__(16) float sh_ha[68], sh_hb[68];   // A: h1,h2 / B: h3,(unused)
    __shared__ __align__(16) float sh_buf[2][68];          // B: h2 double buffer
    __shared__ float sh_za[G4], sh_zb[G4];                 // A: z1,z2 / B: z3,(unused)

    // ---- weights in registers on dot threads (j < 260) ----
    unsigned long long wcol[33], ucol[33];
    float bj = 0.0f;
    if (j < G4) {
#pragma unroll
        for (int m = 0; m < 32; m++) {
            wcol[m] = pack2(W[(2 * m) * G4 + j], W[(2 * m + 1) * G4 + j]);
            ucol[m] = pack2(U[(2 * m) * G4 + j], U[(2 * m + 1) * G4 + j]);
        }
        wcol[32] = pack2(W[64 * G4 + j], 0.0f);
        ucol[32] = pack2(U[64 * G4 + j], 0.0f);
        bj = b[j];
    }
    if (j < 68) {
        sh_ha[j] = 0.0f; sh_hb[j] = 0.0f;
        sh_buf[0][j] = 0.0f; sh_buf[1][j] = 0.0f;
    }

    if (isA) {
        // ================= A: layers 1 + 2, 2 phases/step =================
        const float* __restrict__ zpre = g_zpre + (size_t)row * SEQ * G4;
        float* __restrict__ h2out = g_h2s + (size_t)row * SEQ * UNITS;
        unsigned int* flag = &g_flag[row];

        const bool actA = (j < UNITS);                    // layer-1 act
        const bool actB = (j >= UNITS && j < 2 * UNITS);  // layer-2 act (lagged)
        const int  au = actA ? j : (j - UNITS);
        float c = 0.0f;                                   // c1 (actA) or c2 (actB)

        float zp = 0.f, zp_next = 0.f;                    // rolling zpre prefetch
        if (j < G4) {
            sh_za[j] = zpre[j];                           // z1(0)
            zp = zpre[(size_t)1 * G4 + j];                // zpre(1)
            zp_next = zpre[(size_t)2 * G4 + j];           // zpre(2)
        }
        __syncthreads();

        for (int t = 0; t < SEQ; t++) {
            // ---- P1: acts only ----
            if (j < 2 * UNITS) {
                const float* zarr = actA ? sh_za : sh_zb;
                if (actA || t > 0) {                      // no z2(-1) at t=0
                    float hn = act_lstm(zarr, au, c);
                    if (actA) {
                        sh_ha[au] = hn;                   // h1(t)
                    } else {
                        sh_hb[au] = hn;                   // h2(t-1)
                        h2out[(size_t)(t - 1) * UNITS + au] = hn;
                    }
                }
            }
            __syncthreads();

            // ---- P2: dots only (+ pub on idle w9 lane) ----
            if (j < G4) {
                unsigned long long a0 = 0ull, a1 = 0ull;
                dot33(sh_ha, wcol, a0, a1);               // h1(t)@W
                dot33(sh_hb, ucol, a0, a1);               // + h2(t-1)@U
                float z2 = bj + hsum4(a0, a1);
                a0 = 0ull; a1 = 0ull;
                dot33(sh_ha, ucol, a0, a1);               // h1(t)@U
                float z1n = zp + hsum4(a0, a1);
                sh_zb[j] = z2;                            // z2(t)
                sh_za[j] = z1n;                           // z1(t+1)
                zp = zp_next;
                int ti = (t + 3 < SEQ) ? (t + 3) : (SEQ - 1);
                zp_next = zpre[(size_t)ti * G4 + j];
            } else if (j == 319 && t > 0 && (t & 3) == 0) {
                __threadfence();                          // h2 STGs of steps < t
                st_rel(flag, (unsigned)t);                // h2[0..t-1] available
            }
            __syncthreads();
        }
        // epilogue: h2(SEQ-1) from z2(SEQ-1)
        if (actB) {
            float hn = act_lstm(sh_zb, au, c);
            h2out[(size_t)(SEQ - 1) * UNITS + au] = hn;
        }
        __syncthreads();
        if (j == 319) {                                   // final publication
            __threadfence();
            st_rel(flag, (unsigned)SEQ);
        }
    } else {
        // ================= B: layer 3, 2 phases/step (R11-proven) =================
        const float* __restrict__ h2in = g_h2s + (size_t)row * SEQ * UNITS;
        float* __restrict__ h3out = g_h3 + (size_t)row * SEQ * UNITS;
        const unsigned int* flag = &g_flag[row];
        const int lane = (j >= 288) ? (j - 288) : -1;     // w9 fetch warp
        float c3 = 0.f;

        // initial fetch: h2(0) -> buf[0]
        if (lane >= 0) {
            while (ld_acq(flag) < 1u) __nanosleep(64);
            for (int u = lane; u < UNITS; u += 32)
                sh_buf[0][u] = h2in[u];
        }
        __syncthreads();

        for (int t = 0; t < SEQ; t++) {
            // P1: z3 = h2(t)@W + h3(t-1)@U + b  ||  w9: fetch h2(t+1)
            if (j < G4) {
                unsigned long long a0 = 0ull, a1 = 0ull;
                dot33(sh_buf[t & 1], wcol, a0, a1);
                dot33(sh_ha, ucol, a0, a1);               // sh_ha = h3
                sh_za[j] = bj + hsum4(a0, a1);
            } else if (lane >= 0) {
                int tsrc = (t + 1 < SEQ) ? (t + 1) : (SEQ - 1);
                while (ld_acq(flag) < (unsigned)(tsrc + 1)) __nanosleep(64);
                for (int u = lane; u < UNITS; u += 32)
                    sh_buf[(t + 1) & 1][u] = h2in[(size_t)tsrc * UNITS + u];
            }
            __syncthreads();

            // P2: act3(z3) -> h3, emit
            if (j < UNITS) {
                float hn = act_lstm(sh_za, j, c3);
                sh_ha[j] = hn;
                h3out[(size_t)t * UNITS + j] = hn;
            }
            __syncthreads();
        }
    }
}

// ---------------- kernel 3: out = ys @ Wd + bd  (parallel) ----------------
__global__ void __launch_bounds__(G4) dense_kernel(const float* __restrict__ Wd,
                                                   const float* __restrict__ bd,
                                                   float* __restrict__ out) {
    const int tid = threadIdx.x;           // 0..259
    const int rsub = tid / UNITS;          // 0..3
    const int jl = tid - rsub * UNITS;     // 0..64 -> output column

    unsigned long long wdcol[33];
#pragma unroll
    for (int m = 0; m < 32; m++)
        wdcol[m] = pack2(Wd[(2 * m) * UNITS + jl], Wd[(2 * m + 1) * UNITS + jl]);
    wdcol[32] = pack2(Wd[64 * UNITS + jl], 0.0f);
    const float bj = bd[jl];

    __shared__ __align__(16) float sh_y[4][68];
    if (tid < 12) sh_y[tid / 3][65 + tid % 3] = 0.0f;
    __syncthreads();

    for (size_t row0 = (size_t)blockIdx.x * 4; row0 < NROWS;
         row0 += (size_t)gridDim.x * 4) {
        __syncthreads();
        sh_y[rsub][jl] = g_h3[(row0 + rsub) * UNITS + jl];
        __syncthreads();
        unsigned long long a0 = 0ull, a1 = 0ull;
        dot33(sh_y[rsub], wdcol, a0, a1);
        out[(row0 + rsub) * UNITS + jl] = bj + hsum4(a0, a1);
    }
}

// ---------------- launch ----------------
extern "C" void kernel_launch(void* const* d_in, const int* in_sizes, int n_in,
                              void* d_out, int out_size) {
    const float* x  = (const float*)d_in[0];
    const float* W  = (const float*)d_in[1];
    const float* U  = (const float*)d_in[2];
    const float* b  = (const float*)d_in[3];
    const float* Wd = (const float*)d_in[4];
    const float* bd = (const float*)d_in[5];
    float* out = (float*)d_out;

    init_kernel<<<1, 64>>>();
    pre_kernel<<<1184, G4>>>(x, W, b);
    rec2_kernel<<<2 * BATCH, 320>>>(W, U, b);
    dense_kernel<<<1184, G4>>>(Wd, bd, out);
}

// round 16
// speedup vs baseline: 1.8033x; 1.3496x over previous
#include <cuda_runtime.h>
#include <cstdint>

#define UNITS 65
#define G4    260          // 4*UNITS
#define BATCH 50
#define SEQ   8192
#define NROWS (BATCH * SEQ)   // 409600

// ---------------- scratch (device globals; no runtime allocation) ----------------
__device__ float g_zpre[(size_t)NROWS * G4];     // x@W + b, precomputed per (b,t)
__device__ float g_h2s[(size_t)NROWS * UNITS];   // layer-2 hidden stream (A -> B)
__device__ float g_h3[(size_t)NROWS * UNITS];    // layer-3 hidden states (ys)
__device__ unsigned int g_flag[BATCH];           // per-row h2-entries-available count

// ---------------- f32x2 helpers (Blackwell packed fp32 FMA) ----------------
__device__ __forceinline__ unsigned long long pack2(float lo, float hi) {
    unsigned long long v;
    asm("mov.b64 %0, {%1, %2};" : "=l"(v) : "f"(lo), "f"(hi));
    return v;
}
__device__ __forceinline__ unsigned long long ffma2(unsigned long long a,
                                                    unsigned long long b,
                                                    unsigned long long c) {
    unsigned long long d;
    asm("fma.rn.f32x2 %0, %1, %2, %3;" : "=l"(d) : "l"(a), "l"(b), "l"(c));
    return d;
}
__device__ __forceinline__ unsigned long long fadd2(unsigned long long a,
                                                    unsigned long long b) {
    unsigned long long d;
    asm("add.rn.f32x2 %0, %1, %2;" : "=l"(d) : "l"(a), "l"(b));
    return d;
}
__device__ __forceinline__ float hsum4(unsigned long long a0, unsigned long long a1) {
    unsigned long long s = fadd2(a0, a1);
    float x0, x1;
    asm("mov.b64 {%0, %1}, %2;" : "=f"(x0), "=f"(x1) : "l"(s));
    return x0 + x1;
}

// dot over K=65 (padded to 66 with zero): sh must be 16B-aligned float[68] with
// sh[65] == 0; col[33] holds weight pairs (col[32].hi == 0).
__device__ __forceinline__ void dot33(const float* __restrict__ sh,
                                      const unsigned long long* col,
                                      unsigned long long& a0,
                                      unsigned long long& a1) {
    const ulonglong2* hp = reinterpret_cast<const ulonglong2*>(sh);
#pragma unroll
    for (int m = 0; m < 16; m++) {
        ulonglong2 p = hp[m];
        a0 = ffma2(p.x, col[2 * m + 0], a0);
        a1 = ffma2(p.y, col[2 * m + 1], a1);
    }
    unsigned long long last = *reinterpret_cast<const unsigned long long*>(sh + 64);
    a0 = ffma2(last, col[32], a0);
}

// ---------------- acquire/release flag helpers ----------------
__device__ __forceinline__ unsigned int ld_acq(const unsigned int* p) {
    unsigned int v;
    asm volatile("ld.acquire.gpu.u32 %0, [%1];" : "=r"(v) : "l"(p) : "memory");
    return v;
}
__device__ __forceinline__ void st_rel(unsigned int* p, unsigned int v) {
    asm volatile("st.release.gpu.u32 [%0], %1;" :: "l"(p), "r"(v) : "memory");
}

// ---------------- fast activations (ex2/rcp approx: ~1e-6 rel err) ----------------
__device__ __forceinline__ float fast_ex2(float x) {
    float y; asm("ex2.approx.f32 %0, %1;" : "=f"(y) : "f"(x)); return y;
}
__device__ __forceinline__ float fast_rcp(float x) {
    float y; asm("rcp.approx.f32 %0, %1;" : "=f"(y) : "f"(x)); return y;
}
#define LOG2E 1.4426950408889634f
__device__ __forceinline__ float sigm_f(float x) {
    return fast_rcp(1.0f + fast_ex2(-x * LOG2E));
}
__device__ __forceinline__ float tanh_f(float x) {
    return fmaf(-2.0f, fast_rcp(1.0f + fast_ex2(2.0f * LOG2E * x)), 1.0f);
}
__device__ __forceinline__ float act_lstm(const float* __restrict__ z, int ak,
                                          float& c) {
    float zi = z[ak], zf = z[ak + UNITS];
    float zg = z[ak + 2 * UNITS], zo = z[ak + 3 * UNITS];
    c = sigm_f(zf) * c + sigm_f(zi) * tanh_f(zg);
    return sigm_f(zo) * tanh_f(c);
}

// ---------------- kernel 0: reset flags (every launch / graph replay) ------------
__global__ void init_kernel() {
    if (threadIdx.x < BATCH) g_flag[threadIdx.x] = 0;
}

// ---------------- kernel 1: zpre = x @ W + b  (all rows, parallel) ----------------
__global__ void __launch_bounds__(G4) pre_kernel(const float* __restrict__ x,
                                                 const float* __restrict__ W,
                                                 const float* __restrict__ b) {
    const int tid = threadIdx.x;           // 0..259  -> gate column
    const int rsub = tid / UNITS;          // 0..3    (x-row loader role)
    const int jl = tid - rsub * UNITS;     // 0..64

    unsigned long long wcol[33];
#pragma unroll
    for (int m = 0; m < 32; m++)
        wcol[m] = pack2(W[(2 * m) * G4 + tid], W[(2 * m + 1) * G4 + tid]);
    wcol[32] = pack2(W[64 * G4 + tid], 0.0f);
    const float bj = b[tid];

    __shared__ __align__(16) float sh_x[4][68];
    if (tid < 12) sh_x[tid / 3][65 + tid % 3] = 0.0f;   // zero pads once
    __syncthreads();

    for (size_t row0 = (size_t)blockIdx.x * 4; row0 < NROWS;
         row0 += (size_t)gridDim.x * 4) {
        __syncthreads();   // previous iteration's reads complete
        sh_x[rsub][jl] = x[(row0 + rsub) * UNITS + jl];
        __syncthreads();
#pragma unroll
        for (int r = 0; r < 4; r++) {
            unsigned long long a0 = 0ull, a1 = 0ull;
            dot33(sh_x[r], wcol, a0, a1);
            g_zpre[(row0 + r) * G4 + tid] = bj + hsum4(a0, a1);
        }
    }
}

// ---------------- kernel 2: layer-wavefront recurrence, 2 SMs per batch row ------
// Grid = 100 blocks (single wave on 148 SMs), 384 threads = 12 warps.
// This is the proven R11 schedule (12.36ms) with ONE change: activations moved
// out of the dot warps onto dedicated warps, one unit per thread:
//   w0-w8  (j < 260)     : dot threads (w8 lanes 0-3 only), identical to R11.
//   w9     (j 288..319)  : A: act units 0..31   / B: h2 fetch warp (as R11)
//   w10    (j 320..351)  : A: act units 32..63  / B: idle
//   w11    (j 352..383)  : A: lane0 = act unit 64, lane2 = flag pub (in phase Y,
//                          where w11 is otherwise idle -> zero serialization)
// In R11, threads j<65 executed dot33 (~110cyc) THEN the ~190cyc MUFU act chain
// inside phases X and Z; that serialization is gone. Everything else (phase
// structure, zp prefetch, flag protocol, B block) is unchanged from R11.
//   bid <  50 : "A" block -> layers 1+2, 3 phases/step (X,Y,Z)
//   bid >= 50 : "B" block -> layer 3, 2 phases/step
// Deadlock-freedom: single wave; A never waits on B; A always publishes
// flag=SEQ post-loop; flags reset by init_kernel before rec2 on every replay.
__global__ void __launch_bounds__(384, 1) rec2_kernel(const float* __restrict__ W,
                                                      const float* __restrict__ U,
                                                      const float* __restrict__ b) {
    const int j = threadIdx.x;
    const bool isA = (blockIdx.x < BATCH);
    const int row = isA ? blockIdx.x : (blockIdx.x - BATCH);

    __shared__ __align__(16) float sh_ha[68], sh_hb[68];   // A: h1,h2 / B: h3,(unused)
    __shared__ __align__(16) float sh_buf[2][68];          // B: h2 double buffer
    __shared__ float sh_za[G4], sh_zb[G4];                 // A: z1,z2 / B: z3,(unused)

    // ---- role decode ----
    const bool is_dot = (j < G4);
    const bool is_act = (j >= 288 && j < 352) || (j == 352);
    const int  au = (j == 352) ? 64 : (j - 288);           // act unit
    const bool is_pub = (j == 354);

    // ---- weights in registers on dot threads ----
    unsigned long long wcol[33], ucol[33];
    float bj = 0.0f;
    if (is_dot) {
#pragma unroll
        for (int m = 0; m < 32; m++) {
            wcol[m] = pack2(W[(2 * m) * G4 + j], W[(2 * m + 1) * G4 + j]);
            ucol[m] = pack2(U[(2 * m) * G4 + j], U[(2 * m + 1) * G4 + j]);
        }
        wcol[32] = pack2(W[64 * G4 + j], 0.0f);
        ucol[32] = pack2(U[64 * G4 + j], 0.0f);
        bj = b[j];
    }
    if (j < 68) {
        sh_ha[j] = 0.0f; sh_hb[j] = 0.0f;
        sh_buf[0][j] = 0.0f; sh_buf[1][j] = 0.0f;
    }

    if (isA) {
        // ================= A: layers 1 + 2 (3 phases/step) =================
        const float* __restrict__ zpre = g_zpre + (size_t)row * SEQ * G4;
        float* __restrict__ h2out = g_h2s + (size_t)row * SEQ * UNITS;
        unsigned int* flag = &g_flag[row];

        float c1 = 0.f, c2 = 0.f;            // act-thread cell states (1 unit each)
        float u2v = 0.f, zp = 0.f;

        if (is_dot) sh_za[j] = zpre[j];      // z1(0) = zpre(0)  (h1(-1)=0)
        __syncthreads();

        for (int t = 0; t < SEQ; t++) {
            const size_t tn = (size_t)((t + 1 < SEQ) ? t + 1 : t) * G4;

            // ---- X: dots u2 = h2(t-1)@U + zp prefetch  ||  act1(z1(t))->h1 ----
            if (is_dot) {
                unsigned long long a0 = 0ull, a1 = 0ull;
                dot33(sh_hb, ucol, a0, a1);
                u2v = hsum4(a0, a1);
                zp = zpre[tn + j];
            } else if (is_act) {
                sh_ha[au] = act_lstm(sh_za, au, c1);
            }
            __syncthreads();

            // ---- Y: dots z2 = h1@W + u2 + b  ||  pub (w11, idle otherwise) ----
            if (is_dot) {
                unsigned long long a0 = 0ull, a1 = 0ull;
                dot33(sh_ha, wcol, a0, a1);
                sh_zb[j] = bj + u2v + hsum4(a0, a1);
            } else if (is_pub && t > 0 && (t & 3) == 0) {
                __threadfence();             // h2 STGs of steps < t are pre-barrier
                st_rel(flag, (unsigned)t);   // h2[0..t-1] available
            }
            __syncthreads();

            // ---- Z: dots u1 = h1@U, z1(t+1) = zp + u1  ||  act2(z2)->h2 + STG ----
            if (is_dot) {
                unsigned long long a0 = 0ull, a1 = 0ull;
                dot33(sh_ha, ucol, a0, a1);
                sh_za[j] = zp + hsum4(a0, a1);
            } else if (is_act) {
                float hn = act_lstm(sh_zb, au, c2);
                sh_hb[au] = hn;
                h2out[(size_t)t * UNITS + au] = hn;
            }
            __syncthreads();
        }
        if (is_pub) {                        // final publication (B depends on it)
            __threadfence();
            st_rel(flag, (unsigned)SEQ);
        }
    } else {
        // ================= B: layer 3, 2 phases/step (R11-proven) =================
        const float* __restrict__ h2in = g_h2s + (size_t)row * SEQ * UNITS;
        float* __restrict__ h3out = g_h3 + (size_t)row * SEQ * UNITS;
        const unsigned int* flag = &g_flag[row];
        const int lane = (j >= 288 && j < 320) ? (j - 288) : -1;  // w9 fetch warp
        float c3 = 0.f;

        // initial fetch: h2(0) -> buf[0]
        if (lane >= 0) {
            while (ld_acq(flag) < 1u) __nanosleep(64);
            for (int u = lane; u < UNITS; u += 32)
                sh_buf[0][u] = h2in[u];
        }
        __syncthreads();

        for (int t = 0; t < SEQ; t++) {
            // P1: z3 = h2(t)@W + h3(t-1)@U + b  ||  w9: fetch h2(t+1)
            if (is_dot) {
                unsigned long long a0 = 0ull, a1 = 0ull;
                dot33(sh_buf[t & 1], wcol, a0, a1);
                dot33(sh_ha, ucol, a0, a1);               // sh_ha = h3
                sh_za[j] = bj + hsum4(a0, a1);
            } else if (lane >= 0) {
                int tsrc = (t + 1 < SEQ) ? (t + 1) : (SEQ - 1);
                while (ld_acq(flag) < (unsigned)(tsrc + 1)) __nanosleep(64);
                for (int u = lane; u < UNITS; u += 32)
                    sh_buf[(t + 1) & 1][u] = h2in[(size_t)tsrc * UNITS + u];
            }
            __syncthreads();

            // P2: act3(z3) -> h3, emit (acts inside dot warps: phase is dot-free,
            // so no serialization — proven layout from R11)
            if (j < UNITS) {
                float hn = act_lstm(sh_za, j, c3);
                sh_ha[j] = hn;
                h3out[(size_t)t * UNITS + j] = hn;
            }
            __syncthreads();
        }
    }
}

// ---------------- kernel 3: out = ys @ Wd + bd  (parallel) ----------------
__global__ void __launch_bounds__(G4) dense_kernel(const float* __restrict__ Wd,
                                                   const float* __restrict__ bd,
                                                   float* __restrict__ out) {
    const int tid = threadIdx.x;           // 0..259
    const int rsub = tid / UNITS;          // 0..3
    const int jl = tid - rsub * UNITS;     // 0..64 -> output column

    unsigned long long wdcol[33];
#pragma unroll
    for (int m = 0; m < 32; m++)
        wdcol[m] = pack2(Wd[(2 * m) * UNITS + jl], Wd[(2 * m + 1) * UNITS + jl]);
    wdcol[32] = pack2(Wd[64 * UNITS + jl], 0.0f);
    const float bj = bd[jl];

    __shared__ __align__(16) float sh_y[4][68];
    if (tid < 12) sh_y[tid / 3][65 + tid % 3] = 0.0f;
    __syncthreads();

    for (size_t row0 = (size_t)blockIdx.x * 4; row0 < NROWS;
         row0 += (size_t)gridDim.x * 4) {
        __syncthreads();
        sh_y[rsub][jl] = g_h3[(row0 + rsub) * UNITS + jl];
        __syncthreads();
        unsigned long long a0 = 0ull, a1 = 0ull;
        dot33(sh_y[rsub], wdcol, a0, a1);
        out[(row0 + rsub) * UNITS + jl] = bj + hsum4(a0, a1);
    }
}

// ---------------- launch ----------------
extern "C" void kernel_launch(void* const* d_in, const int* in_sizes, int n_in,
                              void* d_out, int out_size) {
    const float* x  = (const float*)d_in[0];
    const float* W  = (const float*)d_in[1];
    const float* U  = (const float*)d_in[2];
    const float* b  = (const float*)d_in[3];
    const float* Wd = (const float*)d_in[4];
    const float* bd = (const float*)d_in[5];
    float* out = (float*)d_out;

    init_kernel<<<1, 64>>>();
    pre_kernel<<<1184, G4>>>(x, W, b);
    rec2_kernel<<<2 * BATCH, 384>>>(W, U, b);
    dense_kernel<<<1184, G4>>>(Wd, bd, out);
}